// round 16
// baseline (speedup 1.0000x reference)
#include <cuda_runtime.h>
#include <cuda_bf16.h>
#include <stdint.h>
#include <math.h>

#define NB 128
#define NL 512
#define ND 256
#define NH 336
#define NTXT 768
#define NK 16
#define NEMB 128
#define HSCALE 0.15f
#define EPSV 0.05f
#define NITERS 30
#define ALPHAV 1.0f
#define BETAV 0.5f
#define GWV 0.5f
#define TAUV 0.07f
#define SHIFT 56   // max(1, H//6)

// ---------------- device scratch ----------------
__device__ __align__(16) float g_ytir[NB*NH];
__device__ __align__(16) float g_r[NB*NK];
__device__ __align__(16) float g_mu[NB*NK];
__device__ __align__(16) float g_kn[NB*NK*NEMB];
__device__ __align__(16) float g_tsg[NB*ND];
__device__ __align__(16) float g_gate[NB*ND];
__device__ __align__(16) float g_hid[NB*512];
__device__ __align__(16) float g_Wg1T[512*1280];
__device__ __align__(16) float g_Wg2T[256*512];
__device__ __align__(16) float g_Wt2kT[112*768];
__device__ __align__(16) float g_raw[NB*112];
__device__ __align__(16) float g_par[NB*NK*8];
__device__ __align__(16) unsigned g_WcatP[128*384];
__device__ __align__(16) __nv_bfloat16 g_ybf[(size_t)NB*NH*ND];
__device__ __align__(16) float g_T[(size_t)NB*NH*384];
__device__ __align__(16) float g_fpos[(size_t)NB*NH*NEMB];
__device__ __align__(16) float g_invn[NB*NH];
__device__ double g_acc[8];   // 0:mse 1:cot 2:delta 3:ent 4:tv

__device__ __forceinline__ float softplusf(float x){
    return fmaxf(x,0.f) + log1pf(__expf(-fabsf(x)));
}
__device__ __forceinline__ float sigmoidf(float x){
    return 1.f/(1.f+__expf(-x));
}
__device__ __forceinline__ float wcat_elem(const float* __restrict__ Wfp, int c, int j){
    if (j < 128)      return Wfp[c*128+j] + Wfp[(256+c)*128+j] + Wfp[(512+c)*128+j];
    else if (j < 256){ int e=j-128; return Wfp[(256+c)*128+e] + 2.f*Wfp[(512+c)*128+e]; }
    else             { int e=j-256; return Wfp[(512+c)*128+e]; }
}
__device__ __forceinline__ float wredsum(float x){
    #pragma unroll
    for (int o=16;o>0;o>>=1) x += __shfl_down_sync(0xffffffffu,x,o);
    return x;
}

// =============== P1: Wcat pack + transposes + ybf + kB + zero ===============
// blocks: [0,192) Wcat | [192,288) T0 | [288,928) T1 | [928,1056) T2
//         [1056,2400) ybf | [2400,2528) kB
__global__ void __launch_bounds__(256) kP1(const float* __restrict__ Wfp,
        const float* __restrict__ Wt2k, const float* __restrict__ Wg1,
        const float* __restrict__ Wg2, const float* __restrict__ yfut,
        const float* __restrict__ enc){
    __shared__ float t[32][33];
    __shared__ float4 sd[256];
    int bid = blockIdx.x, tid = threadIdx.x;
    if (bid==0 && tid<8) g_acc[tid]=0.0;
    if (bid < 192){
        int idx = bid*256+tid;  // 49152 = 128*384 exactly
        int c2 = idx/384, j = idx%384;
        float v0 = wcat_elem(Wfp, 2*c2,   j);
        float v1 = wcat_elem(Wfp, 2*c2+1, j);
        __nv_bfloat162 p = __floats2bfloat162_rn(v0, v1);
        g_WcatP[idx] = *(unsigned*)&p;
    } else if (bid < 288){
        int r = bid-192; int j0=(r%4)*32, i0=(r/4)*32;
        int tx=tid&31, ty=tid>>5;
        #pragma unroll
        for (int rr=ty; rr<32; rr+=8)
            if (j0+tx < 112) t[rr][tx] = Wt2k[(i0+rr)*112 + j0+tx];
        __syncthreads();
        #pragma unroll
        for (int rr=ty; rr<32; rr+=8)
            if (j0+rr < 112) g_Wt2kT[(j0+rr)*768 + i0+tx] = t[tx][rr];
    } else if (bid < 928){
        int r = bid-288; int j0=(r%16)*32, i0=(r/16)*32;
        int tx=tid&31, ty=tid>>5;
        #pragma unroll
        for (int rr=ty; rr<32; rr+=8) t[rr][tx] = Wg1[(i0+rr)*512 + j0+tx];
        __syncthreads();
        #pragma unroll
        for (int rr=ty; rr<32; rr+=8) g_Wg1T[(j0+rr)*1280 + i0+tx] = t[tx][rr];
    } else if (bid < 1056){
        int r = bid-928; int j0=(r%8)*32, i0=(r/8)*32;
        int tx=tid&31, ty=tid>>5;
        #pragma unroll
        for (int rr=ty; rr<32; rr+=8) t[rr][tx] = Wg2[(i0+rr)*256 + j0+tx];
        __syncthreads();
        #pragma unroll
        for (int rr=ty; rr<32; rr+=8) g_Wg2T[(j0+rr)*512 + i0+tx] = t[tx][rr];
    } else if (bid < 2400){
        const float4* yf4 = (const float4*)yfut;
        uint2* yb2 = (uint2*)g_ybf;
        const int total = NB*NH*ND/4;   // 2752512; 1344 blocks * 256 thr * 8 iters
        for (int i=(bid-1056)*256+tid; i<total; i+=1344*256){
            float4 yf = yf4[i];
            __nv_bfloat162 p0 = __floats2bfloat162_rn(yf.x, yf.y);
            __nv_bfloat162 p1 = __floats2bfloat162_rn(yf.z, yf.w);
            yb2[i] = make_uint2(*(unsigned*)&p0, *(unsigned*)&p1);
        }
    } else {
        int b = bid-2400;
        int d4 = tid&63, part = tid>>6;  // 4 parts x 128 rows
        const float4* p = (const float4*)enc + (size_t)b*NL*64 + d4;
        float4 s = make_float4(0.f,0.f,0.f,0.f);
        for (int l=part*128; l<part*128+128; l++){
            float4 v = p[(size_t)l*64];
            s.x+=v.x; s.y+=v.y; s.z+=v.z; s.w+=v.w;
        }
        sd[tid]=s; __syncthreads();
        if (tid<128){
            float4 o=sd[tid+128];
            sd[tid].x+=o.x; sd[tid].y+=o.y; sd[tid].z+=o.z; sd[tid].w+=o.w;
        }
        __syncthreads();
        if (tid<64){
            float4 v=sd[tid], o=sd[tid+64];
            const float inv = 1.f/(float)NL;
            v.x=(v.x+o.x)*inv; v.y=(v.y+o.y)*inv; v.z=(v.z+o.z)*inv; v.w=(v.w+o.w)*inv;
            ((float4*)g_tsg)[b*64+tid]=v;
        }
    }
}

// =============== M1: bf16 GEMM (ldmatrix A) + kA1 + kC1 ===============
// blocks: [0,1008) GEMM | [1008,1456) A1 (4-batch) | [1456,3504) C1 (4-batch)
#define GA_W 2560
#define GB_BASE 5120
#define GB_W 2176
#define GSM_WORDS (5120+4352)

__device__ __forceinline__ void cpasync16(unsigned dst, const void* src){
    asm volatile("cp.async.ca.shared.global [%0], [%1], 16;\n" :: "r"(dst), "l"(src));
}

__global__ void __launch_bounds__(256) kM1(const float* __restrict__ text,
        const float* __restrict__ varp, const float* __restrict__ bt2k,
        const float* __restrict__ bg1){
    extern __shared__ unsigned smw[];
    int bid = blockIdx.x, tid = threadIdx.x;
    if (bid < 1008){
        unsigned smem_u32 = (unsigned)__cvta_generic_to_shared(smw);
        int m0 = (bid%336)*128, n0 = (bid/336)*128;
        int warp = tid>>5, lane = tid&31;
        int wm = warp & 1, wn = warp >> 1;
        int lr = lane>>2, lc = lane&3;
        unsigned ldsm_base = smem_u32 +
            (unsigned)(((wm*64 + (lane&15))*20 + (lane>>4)*4)*4);
        float acc[4][4][4];
        #pragma unroll
        for (int a=0;a<4;a++)
          #pragma unroll
          for (int b=0;b<4;b++)
            #pragma unroll
            for (int c=0;c<4;c++) acc[a][b][c]=0.f;
        auto ldtile = [&](int tIt, int buf){
            int k0 = tIt*32, k20 = tIt*16;
            #pragma unroll
            for (int j=0;j<2;j++){
                int i = tid + j*256;
                int r = i>>2, c4 = i&3;
                unsigned dst = smem_u32 + (unsigned)((buf*GA_W + r*20 + c4*4)*4);
                cpasync16(dst, g_ybf + (size_t)(m0+r)*256 + k0 + c4*8);
            }
            #pragma unroll
            for (int j=0;j<2;j++){
                int i = tid + j*256;
                int r = i>>5, c4 = i&31;
                unsigned dst = smem_u32 + (unsigned)((GB_BASE + buf*GB_W + r*136 + c4*4)*4);
                cpasync16(dst, g_WcatP + (k20+r)*384 + n0 + c4*4);
            }
            asm volatile("cp.async.commit_group;\n");
        };
        ldtile(0, 0);
        for (int tt=0; tt<8; tt++){
            if (tt<7){ ldtile(tt+1, (tt+1)&1); asm volatile("cp.async.wait_group 1;\n"); }
            else     { asm volatile("cp.async.wait_group 0;\n"); }
            __syncthreads();
            const unsigned* Bb = smw + GB_BASE + (tt&1)*GB_W;
            unsigned abase = ldsm_base + (unsigned)(((tt&1)*GA_W)*4);
            #pragma unroll
            for (int ks=0;ks<2;ks++){
                unsigned af[4][4], bf[4][2];
                #pragma unroll
                for (int mt=0;mt<4;mt++){
                    unsigned addr = abase + (unsigned)((mt*16*20 + ks*8)*4);
                    asm volatile(
                        "ldmatrix.sync.aligned.m8n8.x4.shared.b16 {%0,%1,%2,%3}, [%4];\n"
                        : "=r"(af[mt][0]),"=r"(af[mt][1]),"=r"(af[mt][2]),"=r"(af[mt][3])
                        : "r"(addr));
                }
                #pragma unroll
                for (int nt=0;nt<4;nt++){
                    int n = wn*32 + nt*8 + lr;
                    const unsigned* p = Bb + (ks*8+lc)*136 + n;
                    bf[nt][0]=p[0]; bf[nt][1]=p[4*136];
                }
                #pragma unroll
                for (int mt=0;mt<4;mt++)
                  #pragma unroll
                  for (int nt=0;nt<4;nt++){
                    asm volatile(
                      "mma.sync.aligned.m16n8k16.row.col.f32.bf16.bf16.f32 "
                      "{%0,%1,%2,%3},{%4,%5,%6,%7},{%8,%9},{%0,%1,%2,%3};\n"
                      : "+f"(acc[mt][nt][0]),"+f"(acc[mt][nt][1]),
                        "+f"(acc[mt][nt][2]),"+f"(acc[mt][nt][3])
                      : "r"(af[mt][0]),"r"(af[mt][1]),"r"(af[mt][2]),"r"(af[mt][3]),
                        "r"(bf[nt][0]),"r"(bf[nt][1]));
                  }
            }
            __syncthreads();
        }
        #pragma unroll
        for (int mt=0;mt<4;mt++){
            int r = m0 + wm*64 + mt*16 + lr;
            #pragma unroll
            for (int nt=0;nt<4;nt++){
                int c = n0 + wn*32 + nt*8 + 2*lc;
                *(float2*)&g_T[(size_t)r*384 + c]     = make_float2(acc[mt][nt][0],acc[mt][nt][1]);
                *(float2*)&g_T[(size_t)(r+8)*384 + c] = make_float2(acc[mt][nt][2],acc[mt][nt][3]);
            }
        }
    } else if (bid < 1456){
        int w = (bid-1008)*8 + (tid>>5);   // 3584 warps = 112 j x 32 bg
        int lane = tid&31;
        int j = w%112, bg = w/112;
        int b0 = bg*4;
        const float* wc = g_Wt2kT + j*NTXT;
        const float* t0 = text + (b0+0)*NTXT;
        const float* t1 = text + (b0+1)*NTXT;
        const float* t2 = text + (b0+2)*NTXT;
        const float* t3 = text + (b0+3)*NTXT;
        float a0=0.f,a1=0.f,a2=0.f,a3=0.f;
        #pragma unroll
        for (int it=0; it<24; it++){
            int i = it*32 + lane;
            float wv = wc[i];
            a0 += t0[i]*wv; a1 += t1[i]*wv; a2 += t2[i]*wv; a3 += t3[i]*wv;
        }
        a0=wredsum(a0); a1=wredsum(a1); a2=wredsum(a2); a3=wredsum(a3);
        if (lane==0){
            float bb = bt2k[j];
            g_raw[(b0+0)*112+j]=a0+bb; g_raw[(b0+1)*112+j]=a1+bb;
            g_raw[(b0+2)*112+j]=a2+bb; g_raw[(b0+3)*112+j]=a3+bb;
        }
    } else {
        int w = (bid-1456)*8 + (tid>>5);   // 16384 warps = 512 j x 32 bg
        int lane = tid&31;
        int j = w&511, bg = w>>9;
        int b0 = bg*4;
        const float4* Wt = (const float4*)(g_Wg1T + j*1280);
        float a0=0.f,a1=0.f,a2=0.f,a3=0.f;
        #pragma unroll
        for (int it=0; it<10; it++){
            int i4 = it*32 + lane;
            float4 wv = Wt[i4];
            float4 x0,x1,x2,x3;
            if (i4 < 64){
                x0=((const float4*)g_tsg)[(b0+0)*64+i4]; x1=((const float4*)g_tsg)[(b0+1)*64+i4];
                x2=((const float4*)g_tsg)[(b0+2)*64+i4]; x3=((const float4*)g_tsg)[(b0+3)*64+i4];
            } else if (i4 < 256){
                int o=i4-64;
                x0=((const float4*)text)[(b0+0)*192+o]; x1=((const float4*)text)[(b0+1)*192+o];
                x2=((const float4*)text)[(b0+2)*192+o]; x3=((const float4*)text)[(b0+3)*192+o];
            } else {
                float4 xv=((const float4*)varp)[i4-256];
                x0=xv; x1=xv; x2=xv; x3=xv;
            }
            a0 += x0.x*wv.x + x0.y*wv.y + x0.z*wv.z + x0.w*wv.w;
            a1 += x1.x*wv.x + x1.y*wv.y + x1.z*wv.z + x1.w*wv.w;
            a2 += x2.x*wv.x + x2.y*wv.y + x2.z*wv.z + x2.w*wv.w;
            a3 += x3.x*wv.x + x3.y*wv.y + x3.z*wv.z + x3.w*wv.w;
        }
        a0=wredsum(a0); a1=wredsum(a1); a2=wredsum(a2); a3=wredsum(a3);
        if (lane==0){
            float bb = bg1[j];
            g_hid[(b0+0)*512+j]=fmaxf(a0+bb,0.f); g_hid[(b0+1)*512+j]=fmaxf(a1+bb,0.f);
            g_hid[(b0+2)*512+j]=fmaxf(a2+bb,0.f); g_hid[(b0+3)*512+j]=fmaxf(a3+bb,0.f);
        }
    }
}

// =============== M2: kA2 + kC2 ===============
// blocks: [0,8) A2 | [8,1032) C2 (4-batch)
__global__ void __launch_bounds__(256) kM2(const float* __restrict__ bg2){
    __shared__ float se[256], st[256];
    int bid = blockIdx.x, tid = threadIdx.x;
    if (bid < 8){
        int gt = bid*256 + tid;
        int b = gt>>4, k = gt&15;
        const float* raw = g_raw + b*112 + k*7;
        float mu  = sigmoidf(raw[0]);
        float sig = softplusf(raw[1])*HSCALE + 1e-3f;
        float amp = softplusf(raw[2]);
        float s3=raw[3], s4=raw[4], s5=raw[5], s6=raw[6];
        float mx=fmaxf(fmaxf(s3,s4),fmaxf(s5,s6));
        float e3=__expf(s3-mx),e4=__expf(s4-mx),e5=__expf(s5-mx),e6=__expf(s6-mx);
        float es=e3+e4+e5+e6, ies=1.f/es;
        float w0=e3*ies,w1=e4*ies,w2=e5*ies,w3=e6*ies;
        float* p = g_par + gt*8;
        p[0]=mu; p[1]=1.f/sig; p[2]=amp; p[3]=w0; p[4]=w1; p[5]=w2; p[6]=w3;
        g_mu[gt]=mu;
        float ent=0.f;
        { float c0=fmaxf(w0,1e-8f); ent+=c0*__logf(c0);
          float c1=fmaxf(w1,1e-8f); ent+=c1*__logf(c1);
          float c2=fmaxf(w2,1e-8f); ent+=c2*__logf(c2);
          float c3=fmaxf(w3,1e-8f); ent+=c3*__logf(c3); }
        float tv=0.f;
        if (k>0) tv = fabsf(mu - sigmoidf(g_raw[b*112+(k-1)*7]));
        se[tid]=ent; st[tid]=tv;
        __syncthreads();
        for (int s=128;s>0;s>>=1){
            if (tid<s){ se[tid]+=se[tid+s]; st[tid]+=st[tid+s]; }
            __syncthreads();
        }
        if (tid==0){
            atomicAdd(&g_acc[3],(double)se[0]);
            atomicAdd(&g_acc[4],(double)st[0]);
        }
    } else {
        int w = (bid-8)*8 + (tid>>5);   // 8192 warps = 256 d x 32 bg
        int lane = tid&31;
        int d = w&255, bg = w>>8;
        int b0 = bg*4;
        const float4* Wt = (const float4*)(g_Wg2T + d*512);
        float a0=0.f,a1=0.f,a2=0.f,a3=0.f;
        #pragma unroll
        for (int it=0; it<4; it++){
            int i4 = it*32 + lane;
            float4 wv = Wt[i4];
            float4 h0=((const float4*)g_hid)[(b0+0)*128+i4];
            float4 h1=((const float4*)g_hid)[(b0+1)*128+i4];
            float4 h2=((const float4*)g_hid)[(b0+2)*128+i4];
            float4 h3=((const float4*)g_hid)[(b0+3)*128+i4];
            a0 += h0.x*wv.x + h0.y*wv.y + h0.z*wv.z + h0.w*wv.w;
            a1 += h1.x*wv.x + h1.y*wv.y + h1.z*wv.z + h1.w*wv.w;
            a2 += h2.x*wv.x + h2.y*wv.y + h2.z*wv.z + h2.w*wv.w;
            a3 += h3.x*wv.x + h3.y*wv.y + h3.z*wv.z + h3.w*wv.w;
        }
        a0=wredsum(a0); a1=wredsum(a1); a2=wredsum(a2); a3=wredsum(a3);
        if (lane==0){
            float bb = bg2[d];
            g_gate[(b0+0)*256+d]=sigmoidf(a0+bb); g_gate[(b0+1)*256+d]=sigmoidf(a1+bb);
            g_gate[(b0+2)*256+d]=sigmoidf(a2+bb); g_gate[(b0+3)*256+d]=sigmoidf(a3+bb);
        }
    }
}

// =============== M4: A5-fused (kappa+ytir+r+kemb) + F ===============
// blocks: [0,128) A5f | [128,21632) F (2 rows/block; 21504 blocks = 43008 rows = NB*NH exactly)
__global__ void __launch_bounds__(256) kM4(const float* __restrict__ Wkemb,
        const float* __restrict__ bkemb, const float* __restrict__ bfp){
    __shared__ float kapS[NK*NH];     // 21504 B
    __shared__ float kembS[NK*NEMB];  // 8192 B
    __shared__ float invS[NK];
    int bid = blockIdx.x, tid = threadIdx.x;
    if (bid < 128){
        int b = bid;
        const float invNH = 1.f/(float)NH;
        #pragma unroll
        for (int q=0; q<21; q++){
            int i = tid + q*256;
            if (i < NK*NH){
                int k = i/NH, h = i - k*NH;
                const float* p = g_par + (b*NK+k)*8;
                float t=(h+0.5f)*invNH;
                float z=(t-p[0])*p[1];
                float az=fabsf(z);
                float b0=__expf(-0.5f*z*z);
                float b1=__expf(-az);
                float b2=fmaxf(1.f-az,0.f);
                float b3=(az<=1.f)?0.5f*(1.f+__cosf(3.14159265358979f*z)):0.f;
                kapS[i]=p[2]*(p[3]*b0+p[4]*b1+p[5]*b2+p[6]*b3);
            }
        }
        __syncthreads();
        for (int h=tid; h<NH; h+=256){
            float s=0.f;
            #pragma unroll
            for (int k=0;k<NK;k++) s += kapS[k*NH+h];
            g_ytir[b*NH+h]=s;
        }
        int warp = tid>>5, lane = tid&31;
        #pragma unroll
        for (int rr=0; rr<2; rr++){
            int k = warp*2+rr;
            float s=0.f;
            for (int h=lane; h<NH; h+=32) s += kapS[k*NH+h];
            s = wredsum(s);
            if (lane==0) g_r[b*NK+k] = s + 1e-6f;
        }
        int e = tid&127, half = tid>>7;
        float acc[8];
        #pragma unroll
        for (int kr=0;kr<8;kr++) acc[kr]=bkemb[e];
        for (int h=0;h<NH;h++){
            float w = Wkemb[h*NEMB+e];
            #pragma unroll
            for (int kr=0;kr<8;kr++) acc[kr] += kapS[(half*8+kr)*NH+h]*w;
        }
        #pragma unroll
        for (int kr=0;kr<8;kr++) kembS[(half*8+kr)*NEMB+e]=acc[kr];
        __syncthreads();
        #pragma unroll
        for (int rr=0;rr<2;rr++){
            int kr = warp*2+rr;
            float s=0.f;
            #pragma unroll
            for (int q=0;q<4;q++){ float v=kembS[kr*NEMB+lane+32*q]; s+=v*v; }
            s = wredsum(s);
            if (lane==0) invS[kr]=1.f/(sqrtf(s)+1e-8f);
        }
        __syncthreads();
        float* dst = g_kn + (size_t)b*NK*NEMB;
        #pragma unroll
        for (int kr=0;kr<8;kr++){
            int k = half*8+kr;
            dst[k*NEMB+e]=kembS[k*NEMB+e]*invS[k];
        }
    } else {
        int half = tid>>7, e = tid&127;
        int m = (bid-128)*2 + half;
        int b=m/NH, h=m%NH;
        int m1=b*NH + (h>0?h-1:0);
        int m2=b*NH + (h>1?h-2:0);
        float v = g_T[(size_t)m*384+e] - g_T[(size_t)m1*384+128+e] + g_T[(size_t)m2*384+256+e] + bfp[e];
        g_fpos[(size_t)m*NEMB+e]=v;
        float sq=wredsum(v*v);
        float* wred = kapS;
        if ((tid&31)==0) wred[tid>>5]=sq;
        __syncthreads();
        if ((tid&127)==0){
            float s=wred[half*4]+wred[half*4+1]+wred[half*4+2]+wred[half*4+3];
            g_invn[m]=1.f/(sqrtf(s)+1e-8f);
        }
    }
}

// =============== kG: per-batch Sinkhorn OT + contrastive, + mse D blocks ===============
// blocks: [0,128) OT | [128,5504) D — 5376 blocks * 512 thr = 2752512 = NB*NH*ND/4 exactly
__global__ void __launch_bounds__(512) kG(const int* __restrict__ perm,
        const float* __restrict__ yres, const float* __restrict__ yfut,
        const float* __restrict__ Wtir, const float* __restrict__ btir,
        const float* __restrict__ varp){
    int tid=threadIdx.x;
    extern __shared__ float sm[];
    if (blockIdx.x >= 128){
        // ---- mse ----
        const float4* yr4=(const float4*)yres; const float4* yf4=(const float4*)yfut;
        const float4* g4 =(const float4*)g_gate;
        const float4* wt4=(const float4*)Wtir; const float4* bt4=(const float4*)btir;
        const float4* vp4=(const float4*)varp;
        int i = (int)(blockIdx.x-128)*512 + tid;
        int d4 = i % (ND/4);
        int bh = i / (ND/4);
        int h = bh % NH, b = bh / NH;
        float s = g_ytir[b*NH+h];
        float4 yr=yr4[i], yf=yf4[i];
        float4 wt=wt4[d4], bt=bt4[d4], vp=vp4[d4];
        float4 gg=g4[b*(ND/4)+d4];
        float t0=(s*wt.x+bt.x)*vp.x, t1=(s*wt.y+bt.y)*vp.y;
        float t2=(s*wt.z+bt.z)*vp.z, t3=(s*wt.w+bt.w)*vp.w;
        float h0=yr.x+GWV*gg.x*(t0-yr.x), h1=yr.y+GWV*gg.y*(t1-yr.y);
        float h2=yr.z+GWV*gg.z*(t2-yr.z), h3=yr.w+GWV*gg.w*(t3-yr.w);
        float d0=h0-yf.x, d1=h1-yf.y, d2=h2-yf.z, d3=h3-yf.w;
        float acc = d0*d0 + d1*d1 + d2*d2 + d3*d3;
        float* sred = sm;
        sred[tid]=acc; __syncthreads();
        for (int s2=256;s2>0;s2>>=1){
            if (tid<s2) sred[tid]+=sred[tid+s2];
            __syncthreads();
        }
        if (tid==0) atomicAdd(&g_acc[0],(double)sred[0]);
        return;
    }
    int b=blockIdx.x;
    float* kn   = sm;              // 2048
    float* Csh  = kn+2048;         // 5376
    float* Km   = Csh+5376;        // 5376
    float* ft   = Km+5376;         // 4128
    float* aggp = ft+4128;         // 2048
    float* aggn = aggp+2048;       // 2048
    float* u    = aggn+2048;       // 16
    float* v    = u+16;            // 336
    float* rr   = v+336;           // 16
    float* mus  = rr+16;           // 16
    float* scr  = mus+16;          // 64
    int* permi  = (int*)(scr+64);  // 128

    for (int i=tid;i<NK*NEMB;i+=512) kn[i]=g_kn[b*NK*NEMB+i];
    if (tid<NK){ rr[tid]=g_r[b*NK+tid]; mus[tid]=g_mu[b*NK+tid]; }
    if (tid<NEMB) permi[tid]=perm[tid];
    if (tid<NH) v[tid]=1.f;
    __syncthreads();
    if (tid==0){
        float t=0.f;
        #pragma unroll
        for (int kk=0;kk<NK;kk++) t+=rr[kk];
        scr[63]=1.f/t;
    }
    __syncthreads();
    if (tid<NK) rr[tid]*=scr[63];
    __syncthreads();

    int k    = tid>>5, lane = tid&31;
    int kq   = tid>>7, e    = tid&127;
    int ck   = tid>>5, chh  = tid&31;

    for (int h0=0;h0<NH;h0+=32){
        int hv=min(32,NH-h0);
        for (int i=tid;i<32*128;i+=512){
            int r2=i>>7, c=i&127;
            if (r2<hv) ft[r2*129+c]=g_fpos[((size_t)(b*NH+h0+r2))*NEMB+c];
        }
        __syncthreads();
        if (chh<hv){
            int h=h0+chh;
            float s=0.f;
            const float* knk=&kn[ck*128];
            const float* fr=&ft[chh*129];
            #pragma unroll 8
            for (int ee=0;ee<128;ee++) s+=knk[ee]*fr[ee];
            float cosv = s*g_invn[b*NH+h];
            float t=(h+0.5f)/(float)NH;
            float C = ALPHAV*(1.f-cosv) + BETAV*fmaxf(mus[ck]-t,0.f);
            Csh[ck*NH+h]=C;
            Km[ck*NH+h]=__expf(-C*(1.f/EPSV));
        }
        __syncthreads();
    }

    for (int it=0; it<NITERS; it++){
        {
            float s=0.f;
            for (int h=lane;h<NH;h+=32) s+=Km[k*NH+h]*v[h];
            s=wredsum(s);
            if (lane==0) u[k]=rr[k]/(s+1e-9f);
        }
        __syncthreads();
        if (tid<NH){
            float s=0.f;
            #pragma unroll
            for (int kk=0;kk<NK;kk++) s+=Km[kk*NH+tid]*u[kk];
            v[tid]=(1.f/(float)NH)/(s+1e-9f);
        }
        __syncthreads();
    }

    float cot=0.f;
    for (int i=tid;i<NK*NH;i+=512){
        int kk=i/NH, h=i%NH;
        float pi=u[kk]*Km[i]*v[h];
        Km[i]=pi;
        cot+=Csh[i]*pi;
    }
    cot=wredsum(cot);
    if (lane==0) scr[k]=cot;
    __syncthreads();
    if (tid==0){
        float s=0.f; for (int i=0;i<16;i++) s+=scr[i];
        atomicAdd(&g_acc[1],(double)s);
    }
    {
        float s=0.f;
        for (int h=lane;h<NH;h+=32) s+=Km[k*NH+h];
        s=wredsum(s);
        if (lane==0) scr[16+k]=1.f/(s+1e-9f);
    }
    __syncthreads();
    for (int i=tid;i<NK*NH;i+=512) Km[i]*=scr[16+i/NH];
    __syncthreads();

    float accp[4]={0,0,0,0}, accn[4]={0,0,0,0};
    for (int h0=0;h0<NH;h0+=32){
        int hv=min(32,NH-h0);
        for (int i=tid;i<32*128;i+=512){
            int r2=i>>7, c=i&127;
            if (r2<hv) ft[r2*129+c]=g_fpos[((size_t)(b*NH+h0+r2))*NEMB+c];
        }
        __syncthreads();
        for (int hh=0;hh<hv;hh++){
            float f=ft[hh*129+e];
            int h=h0+hh;
            int hn=h+SHIFT; if (hn>=NH) hn-=NH;
            #pragma unroll
            for (int j=0;j<4;j++){
                int kk=kq*4+j;
                accp[j]+=Km[kk*NH+h ]*f;
                accn[j]+=Km[kk*NH+hn]*f;
            }
        }
        __syncthreads();
    }
    #pragma unroll
    for (int j=0;j<4;j++){
        aggp[(kq*4+j)*128+e]=accp[j];
        aggn[(kq*4+j)*128+e]=accn[j];
    }
    __syncthreads();

    {
        float sp=0,sn=0,dp=0,dn=0,d2=0;
        for (int ee=lane; ee<128; ee+=32){
            float ap=aggp[k*128+ee], an=aggn[k*128+ee], kv=kn[k*128+ee];
            sp+=ap*ap; sn+=an*an; dp+=kv*ap; dn+=kv*an;
            d2+=kv*aggp[k*128+permi[ee]];
        }
        #pragma unroll
        for (int o=16;o>0;o>>=1){
            sp+=__shfl_down_sync(0xffffffffu,sp,o);
            sn+=__shfl_down_sync(0xffffffffu,sn,o);
            dp+=__shfl_down_sync(0xffffffffu,dp,o);
            dn+=__shfl_down_sync(0xffffffffu,dn,o);
            d2+=__shfl_down_sync(0xffffffffu,d2,o);
        }
        if (lane==0){
            float ip=1.f/(sqrtf(sp)+1e-8f), in_=1.f/(sqrtf(sn)+1e-8f);
            float l0=dp*ip*(1.f/TAUV), l1=dn*in_*(1.f/TAUV), l2=d2*ip*(1.f/TAUV);
            float mx=fmaxf(l0,fmaxf(l1,l2));
            float lse=mx+logf(expf(l0-mx)+expf(l1-mx)+expf(l2-mx));
            scr[32+k]=lse-l0;
        }
    }
    __syncthreads();
    if (tid==0){
        float s=0.f; for (int i=0;i<16;i++) s+=scr[32+i];
        atomicAdd(&g_acc[2],(double)s);
    }
}

// ---------------- final combine ----------------
__global__ void kZF(float* out){
    double mse = g_acc[0]/((double)NB*NH*ND);
    double cot = g_acc[1]/(double)NB;
    double del = g_acc[2]/((double)NB*NK);
    double ent = -g_acc[3]/((double)NB*NK);
    double tv  = g_acc[4]/((double)NB*(NK-1));
    out[0]=(float)(1.0*mse + 0.1*cot + 0.1*del + 0.01*ent + 0.01*tv);
}

extern "C" void kernel_launch(void* const* d_in, const int* in_sizes, int n_in,
                              void* d_out, int out_size){
    const float* y_res =(const float*)d_in[0];
    const float* text  =(const float*)d_in[1];
    const float* enc   =(const float*)d_in[2];
    const float* yfut  =(const float*)d_in[3];
    const int*   perm  =(const int*)  d_in[4];
    const float* Wt2k  =(const float*)d_in[5];
    const float* bt2k  =(const float*)d_in[6];
    const float* Wkemb =(const float*)d_in[7];
    const float* bkemb =(const float*)d_in[8];
    const float* Wtir  =(const float*)d_in[9];
    const float* btir  =(const float*)d_in[10];
    const float* varp  =(const float*)d_in[11];
    const float* Wg1   =(const float*)d_in[12];
    const float* bg1   =(const float*)d_in[13];
    const float* Wg2   =(const float*)d_in[14];
    const float* bg2   =(const float*)d_in[15];
    const float* Wfp   =(const float*)d_in[16];
    const float* bfp   =(const float*)d_in[17];
    float* out=(float*)d_out;

    size_t smG = (size_t)(2048+5376+5376+4128+2048+2048+16+336+16+16+64+128)*4;
    size_t smGEMM = (size_t)GSM_WORDS*4;
    cudaFuncSetAttribute(kG, cudaFuncAttributeMaxDynamicSharedMemorySize, (int)(96*1024));
    cudaFuncSetAttribute(kM1, cudaFuncAttributeMaxDynamicSharedMemorySize, (int)(64*1024));

    kP1<<<2528,256>>>(Wfp,Wt2k,Wg1,Wg2,yfut,enc);
    kM1<<<3504,256,smGEMM>>>(text,varp,bt2k,bg1);
    kM2<<<1032,256>>>(bg2);
    kM4<<<21632,256>>>(Wkemb,bkemb,bfp);
    kG<<<5504,512,smG>>>(perm,y_res,yfut,Wtir,btir,varp);
    kZF<<<1,1>>>(out);
}

// round 17
// speedup vs baseline: 1.0076x; 1.0076x over previous
#include <cuda_runtime.h>
#include <cuda_bf16.h>
#include <stdint.h>
#include <math.h>

#define NB 128
#define NL 512
#define ND 256
#define NH 336
#define NTXT 768
#define NK 16
#define NEMB 128
#define HSCALE 0.15f
#define EPSV 0.05f
#define NITERS 30
#define ALPHAV 1.0f
#define BETAV 0.5f
#define GWV 0.5f
#define TAUV 0.07f
#define SHIFT 56   // max(1, H//6)

// ---------------- device scratch ----------------
__device__ __align__(16) float g_ytir[NB*NH];
__device__ __align__(16) float g_r[NB*NK];
__device__ __align__(16) float g_mu[NB*NK];
__device__ __align__(16) float g_kn[NB*NK*NEMB];
__device__ __align__(16) float g_tsg[NB*ND];
__device__ __align__(16) float g_gate[NB*ND];
__device__ __align__(16) float g_hid[NB*512];
__device__ __align__(16) float g_Wg1T[512*1280];
__device__ __align__(16) float g_Wg2T[256*512];
__device__ __align__(16) float g_Wt2kT[112*768];
__device__ __align__(16) float g_raw[NB*112];
__device__ __align__(16) float g_par[NB*NK*8];
__device__ __align__(16) unsigned g_WcatP[128*384];
__device__ __align__(16) __nv_bfloat16 g_ybf[(size_t)NB*NH*ND];
__device__ __align__(16) float g_T[(size_t)NB*NH*384];
__device__ __align__(16) float g_fpos[(size_t)NB*NH*NEMB];
__device__ __align__(16) float g_invn[NB*NH];
__device__ double g_acc[8];   // 0:mse 1:cot 2:delta 3:ent 4:tv

__device__ __forceinline__ float softplusf(float x){
    return fmaxf(x,0.f) + log1pf(__expf(-fabsf(x)));
}
__device__ __forceinline__ float sigmoidf(float x){
    return 1.f/(1.f+__expf(-x));
}
__device__ __forceinline__ float wcat_elem(const float* __restrict__ Wfp, int c, int j){
    if (j < 128)      return Wfp[c*128+j] + Wfp[(256+c)*128+j] + Wfp[(512+c)*128+j];
    else if (j < 256){ int e=j-128; return Wfp[(256+c)*128+e] + 2.f*Wfp[(512+c)*128+e]; }
    else             { int e=j-256; return Wfp[(512+c)*128+e]; }
}
__device__ __forceinline__ float wredsum(float x){
    #pragma unroll
    for (int o=16;o>0;o>>=1) x += __shfl_down_sync(0xffffffffu,x,o);
    return x;
}

// =============== P1: Wcat pack + transposes + ybf + kB + zero ===============
// blocks: [0,192) Wcat | [192,288) T0 | [288,928) T1 | [928,1056) T2
//         [1056,2400) ybf | [2400,2528) kB
__global__ void __launch_bounds__(256) kP1(const float* __restrict__ Wfp,
        const float* __restrict__ Wt2k, const float* __restrict__ Wg1,
        const float* __restrict__ Wg2, const float* __restrict__ yfut,
        const float* __restrict__ enc){
    __shared__ float t[32][33];
    __shared__ float4 sd[256];
    int bid = blockIdx.x, tid = threadIdx.x;
    if (bid==0 && tid<8) g_acc[tid]=0.0;
    if (bid < 192){
        int idx = bid*256+tid;  // 192*256 = 49152 = 128*384 exactly
        int c2 = idx/384, j = idx%384;
        float v0 = wcat_elem(Wfp, 2*c2,   j);
        float v1 = wcat_elem(Wfp, 2*c2+1, j);
        __nv_bfloat162 p = __floats2bfloat162_rn(v0, v1);
        g_WcatP[idx] = *(unsigned*)&p;
    } else if (bid < 288){
        int r = bid-192; int j0=(r%4)*32, i0=(r/4)*32;
        int tx=tid&31, ty=tid>>5;
        #pragma unroll
        for (int rr=ty; rr<32; rr+=8)
            if (j0+tx < 112) t[rr][tx] = Wt2k[(i0+rr)*112 + j0+tx];
        __syncthreads();
        #pragma unroll
        for (int rr=ty; rr<32; rr+=8)
            if (j0+rr < 112) g_Wt2kT[(j0+rr)*768 + i0+tx] = t[tx][rr];
    } else if (bid < 928){
        int r = bid-288; int j0=(r%16)*32, i0=(r/16)*32;
        int tx=tid&31, ty=tid>>5;
        #pragma unroll
        for (int rr=ty; rr<32; rr+=8) t[rr][tx] = Wg1[(i0+rr)*512 + j0+tx];
        __syncthreads();
        #pragma unroll
        for (int rr=ty; rr<32; rr+=8) g_Wg1T[(j0+rr)*1280 + i0+tx] = t[tx][rr];
    } else if (bid < 1056){
        int r = bid-928; int j0=(r%8)*32, i0=(r/8)*32;
        int tx=tid&31, ty=tid>>5;
        #pragma unroll
        for (int rr=ty; rr<32; rr+=8) t[rr][tx] = Wg2[(i0+rr)*256 + j0+tx];
        __syncthreads();
        #pragma unroll
        for (int rr=ty; rr<32; rr+=8) g_Wg2T[(j0+rr)*512 + i0+tx] = t[tx][rr];
    } else if (bid < 2400){
        const float4* yf4 = (const float4*)yfut;
        uint2* yb2 = (uint2*)g_ybf;
        const int total = NB*NH*ND/4;   // 2752512 = 1344 blocks * 256 thr * 8 iters
        for (int i=(bid-1056)*256+tid; i<total; i+=1344*256){
            float4 yf = yf4[i];
            __nv_bfloat162 p0 = __floats2bfloat162_rn(yf.x, yf.y);
            __nv_bfloat162 p1 = __floats2bfloat162_rn(yf.z, yf.w);
            yb2[i] = make_uint2(*(unsigned*)&p0, *(unsigned*)&p1);
        }
    } else {
        int b = bid-2400;
        int d4 = tid&63, part = tid>>6;  // 4 parts x 128 rows
        const float4* p = (const float4*)enc + (size_t)b*NL*64 + d4;
        float4 s = make_float4(0.f,0.f,0.f,0.f);
        for (int l=part*128; l<part*128+128; l++){
            float4 v = p[(size_t)l*64];
            s.x+=v.x; s.y+=v.y; s.z+=v.z; s.w+=v.w;
        }
        sd[tid]=s; __syncthreads();
        if (tid<128){
            float4 o=sd[tid+128];
            sd[tid].x+=o.x; sd[tid].y+=o.y; sd[tid].z+=o.z; sd[tid].w+=o.w;
        }
        __syncthreads();
        if (tid<64){
            float4 v=sd[tid], o=sd[tid+64];
            const float inv = 1.f/(float)NL;
            v.x=(v.x+o.x)*inv; v.y=(v.y+o.y)*inv; v.z=(v.z+o.z)*inv; v.w=(v.w+o.w)*inv;
            ((float4*)g_tsg)[b*64+tid]=v;
        }
    }
}

// =============== M1: bf16 GEMM (ldmatrix A) + kA1 + kC1 ===============
// blocks: [0,1008) GEMM | [1008,1456) A1 (4-batch) | [1456,3504) C1 (4-batch)
#define GA_W 2560
#define GB_BASE 5120
#define GB_W 2176
#define GSM_WORDS (5120+4352)

__device__ __forceinline__ void cpasync16(unsigned dst, const void* src){
    asm volatile("cp.async.ca.shared.global [%0], [%1], 16;\n" :: "r"(dst), "l"(src));
}

__global__ void __launch_bounds__(256) kM1(const float* __restrict__ text,
        const float* __restrict__ varp, const float* __restrict__ bt2k,
        const float* __restrict__ bg1){
    extern __shared__ unsigned smw[];
    int bid = blockIdx.x, tid = threadIdx.x;
    if (bid < 1008){
        unsigned smem_u32 = (unsigned)__cvta_generic_to_shared(smw);
        int m0 = (bid%336)*128, n0 = (bid/336)*128;
        int warp = tid>>5, lane = tid&31;
        int wm = warp & 1, wn = warp >> 1;
        int lr = lane>>2, lc = lane&3;
        unsigned ldsm_base = smem_u32 +
            (unsigned)(((wm*64 + (lane&15))*20 + (lane>>4)*4)*4);
        float acc[4][4][4];
        #pragma unroll
        for (int a=0;a<4;a++)
          #pragma unroll
          for (int b=0;b<4;b++)
            #pragma unroll
            for (int c=0;c<4;c++) acc[a][b][c]=0.f;
        auto ldtile = [&](int tIt, int buf){
            int k0 = tIt*32, k20 = tIt*16;
            #pragma unroll
            for (int j=0;j<2;j++){
                int i = tid + j*256;
                int r = i>>2, c4 = i&3;
                unsigned dst = smem_u32 + (unsigned)((buf*GA_W + r*20 + c4*4)*4);
                cpasync16(dst, g_ybf + (size_t)(m0+r)*256 + k0 + c4*8);
            }
            #pragma unroll
            for (int j=0;j<2;j++){
                int i = tid + j*256;
                int r = i>>5, c4 = i&31;
                unsigned dst = smem_u32 + (unsigned)((GB_BASE + buf*GB_W + r*136 + c4*4)*4);
                cpasync16(dst, g_WcatP + (k20+r)*384 + n0 + c4*4);
            }
            asm volatile("cp.async.commit_group;\n");
        };
        ldtile(0, 0);
        for (int tt=0; tt<8; tt++){
            if (tt<7){ ldtile(tt+1, (tt+1)&1); asm volatile("cp.async.wait_group 1;\n"); }
            else     { asm volatile("cp.async.wait_group 0;\n"); }
            __syncthreads();
            const unsigned* Bb = smw + GB_BASE + (tt&1)*GB_W;
            unsigned abase = ldsm_base + (unsigned)(((tt&1)*GA_W)*4);
            #pragma unroll
            for (int ks=0;ks<2;ks++){
                unsigned af[4][4], bf[4][2];
                #pragma unroll
                for (int mt=0;mt<4;mt++){
                    unsigned addr = abase + (unsigned)((mt*16*20 + ks*8)*4);
                    asm volatile(
                        "ldmatrix.sync.aligned.m8n8.x4.shared.b16 {%0,%1,%2,%3}, [%4];\n"
                        : "=r"(af[mt][0]),"=r"(af[mt][1]),"=r"(af[mt][2]),"=r"(af[mt][3])
                        : "r"(addr));
                }
                #pragma unroll
                for (int nt=0;nt<4;nt++){
                    int n = wn*32 + nt*8 + lr;
                    const unsigned* p = Bb + (ks*8+lc)*136 + n;
                    bf[nt][0]=p[0]; bf[nt][1]=p[4*136];
                }
                #pragma unroll
                for (int mt=0;mt<4;mt++)
                  #pragma unroll
                  for (int nt=0;nt<4;nt++){
                    asm volatile(
                      "mma.sync.aligned.m16n8k16.row.col.f32.bf16.bf16.f32 "
                      "{%0,%1,%2,%3},{%4,%5,%6,%7},{%8,%9},{%0,%1,%2,%3};\n"
                      : "+f"(acc[mt][nt][0]),"+f"(acc[mt][nt][1]),
                        "+f"(acc[mt][nt][2]),"+f"(acc[mt][nt][3])
                      : "r"(af[mt][0]),"r"(af[mt][1]),"r"(af[mt][2]),"r"(af[mt][3]),
                        "r"(bf[nt][0]),"r"(bf[nt][1]));
                  }
            }
            __syncthreads();
        }
        #pragma unroll
        for (int mt=0;mt<4;mt++){
            int r = m0 + wm*64 + mt*16 + lr;
            #pragma unroll
            for (int nt=0;nt<4;nt++){
                int c = n0 + wn*32 + nt*8 + 2*lc;
                *(float2*)&g_T[(size_t)r*384 + c]     = make_float2(acc[mt][nt][0],acc[mt][nt][1]);
                *(float2*)&g_T[(size_t)(r+8)*384 + c] = make_float2(acc[mt][nt][2],acc[mt][nt][3]);
            }
        }
    } else if (bid < 1456){
        int w = (bid-1008)*8 + (tid>>5);   // 3584 warps = 112 j x 32 bg
        int lane = tid&31;
        int j = w%112, bg = w/112;
        int b0 = bg*4;
        const float* wc = g_Wt2kT + j*NTXT;
        const float* t0 = text + (b0+0)*NTXT;
        const float* t1 = text + (b0+1)*NTXT;
        const float* t2 = text + (b0+2)*NTXT;
        const float* t3 = text + (b0+3)*NTXT;
        float a0=0.f,a1=0.f,a2=0.f,a3=0.f;
        #pragma unroll
        for (int it=0; it<24; it++){
            int i = it*32 + lane;
            float wv = wc[i];
            a0 += t0[i]*wv; a1 += t1[i]*wv; a2 += t2[i]*wv; a3 += t3[i]*wv;
        }
        a0=wredsum(a0); a1=wredsum(a1); a2=wredsum(a2); a3=wredsum(a3);
        if (lane==0){
            float bb = bt2k[j];
            g_raw[(b0+0)*112+j]=a0+bb; g_raw[(b0+1)*112+j]=a1+bb;
            g_raw[(b0+2)*112+j]=a2+bb; g_raw[(b0+3)*112+j]=a3+bb;
        }
    } else {
        int w = (bid-1456)*8 + (tid>>5);   // 16384 warps = 512 j x 32 bg
        int lane = tid&31;
        int j = w&511, bg = w>>9;
        int b0 = bg*4;
        const float4* Wt = (const float4*)(g_Wg1T + j*1280);
        float a0=0.f,a1=0.f,a2=0.f,a3=0.f;
        #pragma unroll
        for (int it=0; it<10; it++){
            int i4 = it*32 + lane;
            float4 wv = Wt[i4];
            float4 x0,x1,x2,x3;
            if (i4 < 64){
                x0=((const float4*)g_tsg)[(b0+0)*64+i4]; x1=((const float4*)g_tsg)[(b0+1)*64+i4];
                x2=((const float4*)g_tsg)[(b0+2)*64+i4]; x3=((const float4*)g_tsg)[(b0+3)*64+i4];
            } else if (i4 < 256){
                int o=i4-64;
                x0=((const float4*)text)[(b0+0)*192+o]; x1=((const float4*)text)[(b0+1)*192+o];
                x2=((const float4*)text)[(b0+2)*192+o]; x3=((const float4*)text)[(b0+3)*192+o];
            } else {
                float4 xv=((const float4*)varp)[i4-256];
                x0=xv; x1=xv; x2=xv; x3=xv;
            }
            a0 += x0.x*wv.x + x0.y*wv.y + x0.z*wv.z + x0.w*wv.w;
            a1 += x1.x*wv.x + x1.y*wv.y + x1.z*wv.z + x1.w*wv.w;
            a2 += x2.x*wv.x + x2.y*wv.y + x2.z*wv.z + x2.w*wv.w;
            a3 += x3.x*wv.x + x3.y*wv.y + x3.z*wv.z + x3.w*wv.w;
        }
        a0=wredsum(a0); a1=wredsum(a1); a2=wredsum(a2); a3=wredsum(a3);
        if (lane==0){
            float bb = bg1[j];
            g_hid[(b0+0)*512+j]=fmaxf(a0+bb,0.f); g_hid[(b0+1)*512+j]=fmaxf(a1+bb,0.f);
            g_hid[(b0+2)*512+j]=fmaxf(a2+bb,0.f); g_hid[(b0+3)*512+j]=fmaxf(a3+bb,0.f);
        }
    }
}

// =============== M2: kA2 + kC2 ===============
// blocks: [0,8) A2 | [8,1032) C2 (4-batch)
__global__ void __launch_bounds__(256) kM2(const float* __restrict__ bg2){
    __shared__ float se[256], st[256];
    int bid = blockIdx.x, tid = threadIdx.x;
    if (bid < 8){
        int gt = bid*256 + tid;
        int b = gt>>4, k = gt&15;
        const float* raw = g_raw + b*112 + k*7;
        float mu  = sigmoidf(raw[0]);
        float sig = softplusf(raw[1])*HSCALE + 1e-3f;
        float amp = softplusf(raw[2]);
        float s3=raw[3], s4=raw[4], s5=raw[5], s6=raw[6];
        float mx=fmaxf(fmaxf(s3,s4),fmaxf(s5,s6));
        float e3=__expf(s3-mx),e4=__expf(s4-mx),e5=__expf(s5-mx),e6=__expf(s6-mx);
        float es=e3+e4+e5+e6, ies=1.f/es;
        float w0=e3*ies,w1=e4*ies,w2=e5*ies,w3=e6*ies;
        float* p = g_par + gt*8;
        p[0]=mu; p[1]=1.f/sig; p[2]=amp; p[3]=w0; p[4]=w1; p[5]=w2; p[6]=w3;
        g_mu[gt]=mu;
        float ent=0.f;
        { float c0=fmaxf(w0,1e-8f); ent+=c0*__logf(c0);
          float c1=fmaxf(w1,1e-8f); ent+=c1*__logf(c1);
          float c2=fmaxf(w2,1e-8f); ent+=c2*__logf(c2);
          float c3=fmaxf(w3,1e-8f); ent+=c3*__logf(c3); }
        float tv=0.f;
        if (k>0) tv = fabsf(mu - sigmoidf(g_raw[b*112+(k-1)*7]));
        se[tid]=ent; st[tid]=tv;
        __syncthreads();
        for (int s=128;s>0;s>>=1){
            if (tid<s){ se[tid]+=se[tid+s]; st[tid]+=st[tid+s]; }
            __syncthreads();
        }
        if (tid==0){
            atomicAdd(&g_acc[3],(double)se[0]);
            atomicAdd(&g_acc[4],(double)st[0]);
        }
    } else {
        int w = (bid-8)*8 + (tid>>5);   // 8192 warps = 256 d x 32 bg
        int lane = tid&31;
        int d = w&255, bg = w>>8;
        int b0 = bg*4;
        const float4* Wt = (const float4*)(g_Wg2T + d*512);
        float a0=0.f,a1=0.f,a2=0.f,a3=0.f;
        #pragma unroll
        for (int it=0; it<4; it++){
            int i4 = it*32 + lane;
            float4 wv = Wt[i4];
            float4 h0=((const float4*)g_hid)[(b0+0)*128+i4];
            float4 h1=((const float4*)g_hid)[(b0+1)*128+i4];
            float4 h2=((const float4*)g_hid)[(b0+2)*128+i4];
            float4 h3=((const float4*)g_hid)[(b0+3)*128+i4];
            a0 += h0.x*wv.x + h0.y*wv.y + h0.z*wv.z + h0.w*wv.w;
            a1 += h1.x*wv.x + h1.y*wv.y + h1.z*wv.z + h1.w*wv.w;
            a2 += h2.x*wv.x + h2.y*wv.y + h2.z*wv.z + h2.w*wv.w;
            a3 += h3.x*wv.x + h3.y*wv.y + h3.z*wv.z + h3.w*wv.w;
        }
        a0=wredsum(a0); a1=wredsum(a1); a2=wredsum(a2); a3=wredsum(a3);
        if (lane==0){
            float bb = bg2[d];
            g_gate[(b0+0)*256+d]=sigmoidf(a0+bb); g_gate[(b0+1)*256+d]=sigmoidf(a1+bb);
            g_gate[(b0+2)*256+d]=sigmoidf(a2+bb); g_gate[(b0+3)*256+d]=sigmoidf(a3+bb);
        }
    }
}

// =============== M4: A5-fused (kappa+ytir+r+kemb) + F (warp/row float4) ===============
// blocks: [0,128) A5f | [128,5504) F — 5376 blocks * 8 rows = 43008 = NB*NH exactly
__global__ void __launch_bounds__(256) kM4(const float* __restrict__ Wkemb,
        const float* __restrict__ bkemb, const float* __restrict__ bfp){
    __shared__ float kapS[NK*NH];     // 21504 B
    __shared__ float scr[8*8];        // per-warp norm partials
    __shared__ float invS[NK];
    int bid = blockIdx.x, tid = threadIdx.x;
    if (bid < 128){
        int b = bid;
        const float invNH = 1.f/(float)NH;
        #pragma unroll
        for (int q=0; q<21; q++){
            int i = tid + q*256;
            if (i < NK*NH){
                int k = i/NH, h = i - k*NH;
                const float* p = g_par + (b*NK+k)*8;
                float t=(h+0.5f)*invNH;
                float z=(t-p[0])*p[1];
                float az=fabsf(z);
                float b0=__expf(-0.5f*z*z);
                float b1=__expf(-az);
                float b2=fmaxf(1.f-az,0.f);
                float b3=(az<=1.f)?0.5f*(1.f+__cosf(3.14159265358979f*z)):0.f;
                kapS[i]=p[2]*(p[3]*b0+p[4]*b1+p[5]*b2+p[6]*b3);
            }
        }
        __syncthreads();
        for (int h=tid; h<NH; h+=256){
            float s=0.f;
            #pragma unroll
            for (int k=0;k<NK;k++) s += kapS[k*NH+h];
            g_ytir[b*NH+h]=s;
        }
        int warp = tid>>5, lane = tid&31;
        #pragma unroll
        for (int rr=0; rr<2; rr++){
            int k = warp*2+rr;
            float s=0.f;
            for (int h=lane; h<NH; h+=32) s += kapS[k*NH+h];
            s = wredsum(s);
            if (lane==0) g_r[b*NK+k] = s + 1e-6f;
        }
        // kemb GEMM (acc in regs), norms via per-warp partials
        int e = tid&127, half = tid>>7;
        float acc[8];
        #pragma unroll
        for (int kr=0;kr<8;kr++) acc[kr]=bkemb[e];
        for (int h=0;h<NH;h++){
            float w = Wkemb[h*NEMB+e];
            #pragma unroll
            for (int kr=0;kr<8;kr++) acc[kr] += kapS[(half*8+kr)*NH+h]*w;
        }
        #pragma unroll
        for (int kr=0;kr<8;kr++){
            float s = wredsum(acc[kr]*acc[kr]);
            if (lane==0) scr[warp*8+kr]=s;
        }
        __syncthreads();
        if (tid<NK){
            int hf=tid>>3, kr=tid&7;
            int w0=hf*4;
            float s = scr[(w0+0)*8+kr]+scr[(w0+1)*8+kr]+scr[(w0+2)*8+kr]+scr[(w0+3)*8+kr];
            invS[tid]=1.f/(sqrtf(s)+1e-8f);
        }
        __syncthreads();
        float* dst = g_kn + (size_t)b*NK*NEMB;
        #pragma unroll
        for (int kr=0;kr<8;kr++){
            int k = half*8+kr;
            dst[k*NEMB+e]=acc[kr]*invS[k];
        }
    } else {
        // F: one warp per row, float4 per lane
        int warp = tid>>5, lane = tid&31;
        int m = (bid-128)*8 + warp;
        int b=m/NH, h=m%NH;
        int m1=b*NH + (h>0?h-1:0);
        int m2=b*NH + (h>1?h-2:0);
        float4 t0 = *(const float4*)&g_T[(size_t)m*384      + lane*4];
        float4 t1 = *(const float4*)&g_T[(size_t)m1*384+128 + lane*4];
        float4 t2 = *(const float4*)&g_T[(size_t)m2*384+256 + lane*4];
        float4 bf = ((const float4*)bfp)[lane];
        float4 v;
        v.x = t0.x - t1.x + t2.x + bf.x;
        v.y = t0.y - t1.y + t2.y + bf.y;
        v.z = t0.z - t1.z + t2.z + bf.z;
        v.w = t0.w - t1.w + t2.w + bf.w;
        *(float4*)&g_fpos[(size_t)m*NEMB + lane*4] = v;
        float sq = wredsum(v.x*v.x + v.y*v.y + v.z*v.z + v.w*v.w);
        if (lane==0) g_invn[m]=1.f/(sqrtf(sq)+1e-8f);
    }
}

// =============== kD: mse, tiny smem, full occupancy ===============
// 2688 blocks * 256 thr * 4 iters = 2752512 = NB*NH*ND/4 exactly
__global__ void __launch_bounds__(256) kD(const float* __restrict__ yres,
        const float* __restrict__ yfut, const float* __restrict__ Wtir,
        const float* __restrict__ btir, const float* __restrict__ varp){
    const float4* yr4=(const float4*)yres; const float4* yf4=(const float4*)yfut;
    const float4* g4 =(const float4*)g_gate;
    const float4* wt4=(const float4*)Wtir; const float4* bt4=(const float4*)btir;
    const float4* vp4=(const float4*)varp;
    float acc=0.f;
    const int total = NB*NH*ND/4;
    for (int i=blockIdx.x*256+threadIdx.x; i<total; i+=2688*256){
        int d4 = i % (ND/4);
        int bh = i / (ND/4);
        int h = bh % NH, b = bh / NH;
        float s = g_ytir[b*NH+h];
        float4 yr=yr4[i], yf=yf4[i];
        float4 wt=wt4[d4], bt=bt4[d4], vp=vp4[d4];
        float4 gg=g4[b*(ND/4)+d4];
        float t0=(s*wt.x+bt.x)*vp.x, t1=(s*wt.y+bt.y)*vp.y;
        float t2=(s*wt.z+bt.z)*vp.z, t3=(s*wt.w+bt.w)*vp.w;
        float h0=yr.x+GWV*gg.x*(t0-yr.x), h1=yr.y+GWV*gg.y*(t1-yr.y);
        float h2=yr.z+GWV*gg.z*(t2-yr.z), h3=yr.w+GWV*gg.w*(t3-yr.w);
        float d0=h0-yf.x, d1=h1-yf.y, d2=h2-yf.z, d3=h3-yf.w;
        acc += d0*d0 + d1*d1 + d2*d2 + d3*d3;
    }
    acc = wredsum(acc);
    __shared__ float sred[8];
    if ((threadIdx.x&31)==0) sred[threadIdx.x>>5]=acc;
    __syncthreads();
    if (threadIdx.x==0){
        float s=0.f;
        #pragma unroll
        for (int i=0;i<8;i++) s+=sred[i];
        atomicAdd(&g_acc[0],(double)s);
    }
}

// =============== kG: per-batch Sinkhorn OT + contrastive ===============
__global__ void __launch_bounds__(512) kG(const int* __restrict__ perm){
    int b=blockIdx.x, tid=threadIdx.x;
    extern __shared__ float sm[];
    float* kn   = sm;              // 2048
    float* Csh  = kn+2048;         // 5376
    float* Km   = Csh+5376;        // 5376
    float* ft   = Km+5376;         // 4128
    float* aggp = ft+4128;         // 2048
    float* aggn = aggp+2048;       // 2048
    float* u    = aggn+2048;       // 16
    float* v    = u+16;            // 336
    float* rr   = v+336;           // 16
    float* mus  = rr+16;           // 16
    float* scr  = mus+16;          // 64
    int* permi  = (int*)(scr+64);  // 128

    for (int i=tid;i<NK*NEMB;i+=512) kn[i]=g_kn[b*NK*NEMB+i];
    if (tid<NK){ rr[tid]=g_r[b*NK+tid]; mus[tid]=g_mu[b*NK+tid]; }
    if (tid<NEMB) permi[tid]=perm[tid];
    if (tid<NH) v[tid]=1.f;
    __syncthreads();
    if (tid==0){
        float t=0.f;
        #pragma unroll
        for (int kk=0;kk<NK;kk++) t+=rr[kk];
        scr[63]=1.f/t;
    }
    __syncthreads();
    if (tid<NK) rr[tid]*=scr[63];
    __syncthreads();

    int k    = tid>>5, lane = tid&31;
    int kq   = tid>>7, e    = tid&127;
    int ck   = tid>>5, chh  = tid&31;

    for (int h0=0;h0<NH;h0+=32){
        int hv=min(32,NH-h0);
        for (int i=tid;i<32*128;i+=512){
            int r2=i>>7, c=i&127;
            if (r2<hv) ft[r2*129+c]=g_fpos[((size_t)(b*NH+h0+r2))*NEMB+c];
        }
        __syncthreads();
        if (chh<hv){
            int h=h0+chh;
            float s=0.f;
            const float* knk=&kn[ck*128];
            const float* fr=&ft[chh*129];
            #pragma unroll 8
            for (int ee=0;ee<128;ee++) s+=knk[ee]*fr[ee];
            float cosv = s*g_invn[b*NH+h];
            float t=(h+0.5f)/(float)NH;
            float C = ALPHAV*(1.f-cosv) + BETAV*fmaxf(mus[ck]-t,0.f);
            Csh[ck*NH+h]=C;
            Km[ck*NH+h]=__expf(-C*(1.f/EPSV));
        }
        __syncthreads();
    }

    for (int it=0; it<NITERS; it++){
        {
            float s=0.f;
            for (int h=lane;h<NH;h+=32) s+=Km[k*NH+h]*v[h];
            s=wredsum(s);
            if (lane==0) u[k]=rr[k]/(s+1e-9f);
        }
        __syncthreads();
        if (tid<NH){
            float s=0.f;
            #pragma unroll
            for (int kk=0;kk<NK;kk++) s+=Km[kk*NH+tid]*u[kk];
            v[tid]=(1.f/(float)NH)/(s+1e-9f);
        }
        __syncthreads();
    }

    float cot=0.f;
    for (int i=tid;i<NK*NH;i+=512){
        int kk=i/NH, h=i%NH;
        float pi=u[kk]*Km[i]*v[h];
        Km[i]=pi;
        cot+=Csh[i]*pi;
    }
    cot=wredsum(cot);
    if (lane==0) scr[k]=cot;
    __syncthreads();
    if (tid==0){
        float s=0.f; for (int i=0;i<16;i++) s+=scr[i];
        atomicAdd(&g_acc[1],(double)s);
    }
    {
        float s=0.f;
        for (int h=lane;h<NH;h+=32) s+=Km[k*NH+h];
        s=wredsum(s);
        if (lane==0) scr[16+k]=1.f/(s+1e-9f);
    }
    __syncthreads();
    for (int i=tid;i<NK*NH;i+=512) Km[i]*=scr[16+i/NH];
    __syncthreads();

    float accp[4]={0,0,0,0}, accn[4]={0,0,0,0};
    for (int h0=0;h0<NH;h0+=32){
        int hv=min(32,NH-h0);
        for (int i=tid;i<32*128;i+=512){
            int r2=i>>7, c=i&127;
            if (r2<hv) ft[r2*129+c]=g_fpos[((size_t)(b*NH+h0+r2))*NEMB+c];
        }
        __syncthreads();
        for (int hh=0;hh<hv;hh++){
            float f=ft[hh*129+e];
            int h=h0+hh;
            int hn=h+SHIFT; if (hn>=NH) hn-=NH;
            #pragma unroll
            for (int j=0;j<4;j++){
                int kk=kq*4+j;
                accp[j]+=Km[kk*NH+h ]*f;
                accn[j]+=Km[kk*NH+hn]*f;
            }
        }
        __syncthreads();
    }
    #pragma unroll
    for (int j=0;j<4;j++){
        aggp[(kq*4+j)*128+e]=accp[j];
        aggn[(kq*4+j)*128+e]=accn[j];
    }
    __syncthreads();

    {
        float sp=0,sn=0,dp=0,dn=0,d2=0;
        for (int ee=lane; ee<128; ee+=32){
            float ap=aggp[k*128+ee], an=aggn[k*128+ee], kv=kn[k*128+ee];
            sp+=ap*ap; sn+=an*an; dp+=kv*ap; dn+=kv*an;
            d2+=kv*aggp[k*128+permi[ee]];
        }
        #pragma unroll
        for (int o=16;o>0;o>>=1){
            sp+=__shfl_down_sync(0xffffffffu,sp,o);
            sn+=__shfl_down_sync(0xffffffffu,sn,o);
            dp+=__shfl_down_sync(0xffffffffu,dp,o);
            dn+=__shfl_down_sync(0xffffffffu,dn,o);
            d2+=__shfl_down_sync(0xffffffffu,d2,o);
        }
        if (lane==0){
            float ip=1.f/(sqrtf(sp)+1e-8f), in_=1.f/(sqrtf(sn)+1e-8f);
            float l0=dp*ip*(1.f/TAUV), l1=dn*in_*(1.f/TAUV), l2=d2*ip*(1.f/TAUV);
            float mx=fmaxf(l0,fmaxf(l1,l2));
            float lse=mx+logf(expf(l0-mx)+expf(l1-mx)+expf(l2-mx));
            scr[32+k]=lse-l0;
        }
    }
    __syncthreads();
    if (tid==0){
        float s=0.f; for (int i=0;i<16;i++) s+=scr[32+i];
        atomicAdd(&g_acc[2],(double)s);
    }
}

// ---------------- final combine ----------------
__global__ void kZF(float* out){
    double mse = g_acc[0]/((double)NB*NH*ND);
    double cot = g_acc[1]/(double)NB;
    double del = g_acc[2]/((double)NB*NK);
    double ent = -g_acc[3]/((double)NB*NK);
    double tv  = g_acc[4]/((double)NB*(NK-1));
    out[0]=(float)(1.0*mse + 0.1*cot + 0.1*del + 0.01*ent + 0.01*tv);
}

extern "C" void kernel_launch(void* const* d_in, const int* in_sizes, int n_in,
                              void* d_out, int out_size){
    const float* y_res =(const float*)d_in[0];
    const float* text  =(const float*)d_in[1];
    const float* enc   =(const float*)d_in[2];
    const float* yfut  =(const float*)d_in[3];
    const int*   perm  =(const int*)  d_in[4];
    const float* Wt2k  =(const float*)d_in[5];
    const float* bt2k  =(const float*)d_in[6];
    const float* Wkemb =(const float*)d_in[7];
    const float* bkemb =(const float*)d_in[8];
    const float* Wtir  =(const float*)d_in[9];
    const float* btir  =(const float*)d_in[10];
    const float* varp  =(const float*)d_in[11];
    const float* Wg1   =(const float*)d_in[12];
    const float* bg1   =(const float*)d_in[13];
    const float* Wg2   =(const float*)d_in[14];
    const float* bg2   =(const float*)d_in[15];
    const float* Wfp   =(const float*)d_in[16];
    const float* bfp   =(const float*)d_in[17];
    float* out=(float*)d_out;

    size_t smG = (size_t)(2048+5376+5376+4128+2048+2048+16+336+16+16+64+128)*4;
    size_t smGEMM = (size_t)GSM_WORDS*4;
    cudaFuncSetAttribute(kG, cudaFuncAttributeMaxDynamicSharedMemorySize, (int)(96*1024));
    cudaFuncSetAttribute(kM1, cudaFuncAttributeMaxDynamicSharedMemorySize, (int)(64*1024));

    kP1<<<2528,256>>>(Wfp,Wt2k,Wg1,Wg2,yfut,enc);
    kM1<<<3504,256,smGEMM>>>(text,varp,bt2k,bg1);
    kM2<<<1032,256>>>(bg2);
    kM4<<<5504,256>>>(Wkemb,bkemb,bfp);
    kD<<<2688,256>>>(y_res,yfut,Wtir,btir,varp);
    kG<<<NB,512,smG>>>(perm);
    kZF<<<1,1>>>(out);
}